// round 7
// baseline (speedup 1.0000x reference)
#include <cuda_runtime.h>
#include <cuda_bf16.h>
#include <cstdint>

#define NP   200000
#define NU   50000
#define NNZE 2000000
#define DIM  64
#define NTOT (NP*DIM)      /* 12,800,000 */
#define MSGN (NU*DIM)      /*  3,200,000 */

#define UP_BLOCKS   ((NU * 32) / 256)    /* 6250  */
#define MASK_BLOCKS ((NTOT / 256) / 8)   /* 6250: 8 warps/block, 256 elems/warp */
#define PU_BLOCKS   ((NP * 32) / 256)    /* 25000 */
#define MASK_WORDS  (NTOT / 32)          /* 400000 */

__device__ __align__(16) float g_x[NTOT];
__device__ __align__(16) float g_acc[NTOT];
__device__ __align__(16) __nv_bfloat162 g_xh[NTOT / 2];    // bf16 mirror of x (gather operand)
__device__ __align__(16) __nv_bfloat162 g_msgh[MSGN / 2];  // bf16 msg (gather operand)
__device__ uint32_t g_mask[MASK_WORDS];                    // packed drop bits, per layer

// CSR scratch
__device__ int  g_up_ptr[NU + 1];
__device__ int  g_up_off[NU];
__device__ int2 g_up_cv[NNZE];     // packed (col, val-bits), row-grouped
__device__ int  g_pu_ptr[NP + 1];
__device__ int  g_pu_off[NP];
__device__ int2 g_pu_cv[NNZE];
__device__ int  g_bsum[256];

// ---------------- threefry2x32 (exact JAX semantics) ----------------
__host__ __device__ __forceinline__ uint32_t rotl32(uint32_t x, int d) {
    return (x << d) | (x >> (32 - d));
}

__host__ __device__ __forceinline__ void tf2x32(uint32_t k0, uint32_t k1,
                                                uint32_t x0, uint32_t x1,
                                                uint32_t &o0, uint32_t &o1) {
    uint32_t ks2 = k0 ^ k1 ^ 0x1BD11BDAu;
    x0 += k0; x1 += k1;
#define TFR(r) { x0 += x1; x1 = rotl32(x1, (r)); x1 ^= x0; }
    TFR(13) TFR(15) TFR(26) TFR(6)
    x0 += k1;  x1 += ks2 + 1u;
    TFR(17) TFR(29) TFR(16) TFR(24)
    x0 += ks2; x1 += k0 + 2u;
    TFR(13) TFR(15) TFR(26) TFR(6)
    x0 += k0;  x1 += k1 + 3u;
    TFR(17) TFR(29) TFR(16) TFR(24)
    x0 += k1;  x1 += ks2 + 4u;
    TFR(13) TFR(15) TFR(26) TFR(6)
    x0 += ks2; x1 += k0 + 5u;
#undef TFR
    o0 = x0; o1 = x1;
}

// partitionable threefry draw for element e (counter (0, e)), 32-bit: out0 ^ out1
__device__ __forceinline__ uint32_t tf_bits(uint32_t k0, uint32_t k1, uint32_t e) {
    uint32_t o0, o1;
    tf2x32(k0, k1, 0u, e, o0, o1);
    return o0 ^ o1;
}

// ---------------- CSR build ----------------
__global__ void zero_cnt_kernel() {
    int i = blockIdx.x * blockDim.x + threadIdx.x;
    if (i <= NU) g_up_ptr[i] = 0;
    if (i <= NP) g_pu_ptr[i] = 0;
}

__global__ void hist_kernel(const int4* __restrict__ up_rows,
                            const int4* __restrict__ pu_rows) {
    int e = blockIdx.x * blockDim.x + threadIdx.x;
    if (e >= NNZE / 4) return;
    int4 a = __ldg(up_rows + e);
    atomicAdd(&g_up_ptr[a.x], 1); atomicAdd(&g_up_ptr[a.y], 1);
    atomicAdd(&g_up_ptr[a.z], 1); atomicAdd(&g_up_ptr[a.w], 1);
    int4 b = __ldg(pu_rows + e);
    atomicAdd(&g_pu_ptr[b.x], 1); atomicAdd(&g_pu_ptr[b.y], 1);
    atomicAdd(&g_pu_ptr[b.z], 1); atomicAdd(&g_pu_ptr[b.w], 1);
}

// pass 1: per-block (1024) exclusive scan; excl -> off, block total -> g_bsum
__global__ void scan1_kernel(const int* __restrict__ cnt, int* __restrict__ excl,
                             int n) {
    __shared__ int ws[32];
    int t = threadIdx.x;
    int i = blockIdx.x * 1024 + t;
    int v = (i < n) ? cnt[i] : 0;
    int x = v;
#pragma unroll
    for (int d = 1; d < 32; d <<= 1) {
        int u = __shfl_up_sync(~0u, x, d);
        if ((t & 31) >= d) x += u;
    }
    if ((t & 31) == 31) ws[t >> 5] = x;
    __syncthreads();
    if (t < 32) {
        int w = ws[t];
#pragma unroll
        for (int d = 1; d < 32; d <<= 1) {
            int u = __shfl_up_sync(~0u, w, d);
            if (t >= d) w += u;
        }
        ws[t] = w;
    }
    __syncthreads();
    int base = (t >= 32) ? ws[(t >> 5) - 1] : 0;
    int incl = x + base;
    if (i < n) excl[i] = incl - v;
    if (t == 1023) g_bsum[blockIdx.x] = incl;
}

// pass 2: exclusive scan of <=256 block sums in place; total -> ptr[n]
__global__ void scan2_kernel(int nb, int* __restrict__ ptr_n) {
    __shared__ int ws[8];
    int t = threadIdx.x;       // 256 threads
    int v = (t < nb) ? g_bsum[t] : 0;
    int x = v;
#pragma unroll
    for (int d = 1; d < 32; d <<= 1) {
        int u = __shfl_up_sync(~0u, x, d);
        if ((t & 31) >= d) x += u;
    }
    if ((t & 31) == 31) ws[t >> 5] = x;
    __syncthreads();
    if (t < 8) {
        int w = ws[t];
#pragma unroll
        for (int d = 1; d < 8; d <<= 1) {
            int u = __shfl_up_sync(0xffu, w, d);
            if (t >= d) w += u;
        }
        ws[t] = w;
    }
    __syncthreads();
    int base = (t >= 32) ? ws[(t >> 5) - 1] : 0;
    int incl = x + base;
    if (t < nb) g_bsum[t] = incl - v;
    if (t == nb - 1) *ptr_n = incl;
}

// pass 3: add block offset; write both ptr and off
__global__ void scan3_kernel(int* __restrict__ ptr, int* __restrict__ off, int n) {
    int i = blockIdx.x * 1024 + threadIdx.x;
    if (i < n) {
        int v = off[i] + g_bsum[blockIdx.x];
        ptr[i] = v;
        off[i] = v;
    }
}

__global__ void scatter_kernel(const int4* __restrict__ up_rows,
                               const int4* __restrict__ up_cols,
                               const float4* __restrict__ up_vals,
                               const int4* __restrict__ pu_rows,
                               const int4* __restrict__ pu_cols,
                               const float4* __restrict__ pu_vals) {
    int e = blockIdx.x * blockDim.x + threadIdx.x;
    if (e >= NNZE / 4) return;
    {
        int4 r = __ldg(up_rows + e);
        int4 c = __ldg(up_cols + e);
        float4 v = __ldg(up_vals + e);
        g_up_cv[atomicAdd(&g_up_off[r.x], 1)] = make_int2(c.x, __float_as_int(v.x));
        g_up_cv[atomicAdd(&g_up_off[r.y], 1)] = make_int2(c.y, __float_as_int(v.y));
        g_up_cv[atomicAdd(&g_up_off[r.z], 1)] = make_int2(c.z, __float_as_int(v.z));
        g_up_cv[atomicAdd(&g_up_off[r.w], 1)] = make_int2(c.w, __float_as_int(v.w));
    }
    {
        int4 r = __ldg(pu_rows + e);
        int4 c = __ldg(pu_cols + e);
        float4 v = __ldg(pu_vals + e);
        g_pu_cv[atomicAdd(&g_pu_off[r.x], 1)] = make_int2(c.x, __float_as_int(v.x));
        g_pu_cv[atomicAdd(&g_pu_off[r.y], 1)] = make_int2(c.y, __float_as_int(v.y));
        g_pu_cv[atomicAdd(&g_pu_off[r.z], 1)] = make_int2(c.z, __float_as_int(v.z));
        g_pu_cv[atomicAdd(&g_pu_off[r.w], 1)] = make_int2(c.w, __float_as_int(v.w));
    }
}

// ---------------- fp32 -> bf16 mirror (layer 0 only) ----------------
__global__ void cvt_kernel(const float4* __restrict__ src) {
    int i = blockIdx.x * blockDim.x + threadIdx.x;   // one float4 -> two bf162
    if (i >= NTOT / 4) return;
    float4 v = src[i];
    g_xh[2 * i]     = __floats2bfloat162_rn(v.x, v.y);
    g_xh[2 * i + 1] = __floats2bfloat162_rn(v.z, v.w);
}

// ---------------- UP SpMM + mask generation (one launch, split grid) --------
// blocks [0, UP_BLOCKS): warp-per-U-row SpMM with shfl-batched cv loads.
// blocks [UP_BLOCKS, UP_BLOCKS+MASK_BLOCKS): packed dropout masks for layer l.
__global__ void up_mask_kernel(uint32_t k0, uint32_t k1) {
    int lane = threadIdx.x & 31;
    if (blockIdx.x < UP_BLOCKS) {
        int w = (blockIdx.x * 256 + threadIdx.x) >> 5;   // < NU by construction
        int s = __ldg(g_up_ptr + w), e = __ldg(g_up_ptr + w + 1);
        float accx = 0.f, accy = 0.f;
        for (int base = s; base < e; base += 32) {
            int n = min(32, e - base);
            int2 cv = (base + lane < e) ? __ldg(g_up_cv + base + lane)
                                        : make_int2(0, 0);
            for (int j = 0; j < n; ++j) {
                int   col = __shfl_sync(~0u, cv.x, j);
                float v   = __int_as_float(__shfl_sync(~0u, cv.y, j));
                float2 xv = __bfloat1622float2(g_xh[(size_t)col * (DIM / 2) + lane]);
                accx += v * xv.x;
                accy += v * xv.y;
            }
        }
        g_msgh[(size_t)w * (DIM / 2) + lane] = __floats2bfloat162_rn(accx, accy);
    } else {
        // maskgen: warp wm covers elements [wm*256, wm*256+256)
        int wm = ((blockIdx.x - UP_BLOCKS) * 256 + threadIdx.x) >> 5;
        uint32_t ebase = (uint32_t)wm * 256u + (uint32_t)lane;
#pragma unroll
        for (int i = 0; i < 8; ++i) {
            uint32_t bits = tf_bits(k0, k1, ebase + (uint32_t)(i * 32));
            uint32_t bal = __ballot_sync(~0u, bits >> 31);   // 1 = drop
            if (lane == 0) g_mask[wm * 8 + i] = bal;
        }
    }
}

// ---------------- PU SpMM fused with residual + dropout + acc ----------------
__global__ void spmm_pu_fused_kernel(const float* __restrict__ x_in,
                                     const float* __restrict__ acc_in,
                                     int last, float* __restrict__ out) {
    int w = (blockIdx.x * 256 + threadIdx.x) >> 5;       // < NP by construction
    int lane = threadIdx.x & 31;
    int s = __ldg(g_pu_ptr + w), e = __ldg(g_pu_ptr + w + 1);
    float accx = 0.f, accy = 0.f;
    for (int base = s; base < e; base += 32) {
        int n = min(32, e - base);
        int2 cv = (base + lane < e) ? __ldg(g_pu_cv + base + lane)
                                    : make_int2(0, 0);
        for (int j = 0; j < n; ++j) {
            int   col = __shfl_sync(~0u, cv.x, j);
            float v   = __int_as_float(__shfl_sync(~0u, cv.y, j));
            float2 xv = __bfloat1622float2(g_msgh[(size_t)col * (DIM / 2) + lane]);
            accx += v * xv.x;
            accy += v * xv.y;
        }
    }
    size_t idx = (size_t)w * DIM + lane * 2;

    uint32_t word = __ldg(&g_mask[2 * w + (lane >> 4)]);
    int sh = (lane & 15) * 2;

    float2 xv = *reinterpret_cast<const float2*>(x_in + idx);
    float2 av = *reinterpret_cast<const float2*>(acc_in + idx);
    float n0 = ((word >> sh)       & 1u) ? 0.f : 2.f * (accx + xv.x);
    float n1 = ((word >> (sh + 1)) & 1u) ? 0.f : 2.f * (accy + xv.y);
    float a0 = av.x + n0;
    float a1 = av.y + n1;

    if (last) {
        *reinterpret_cast<float2*>(out + idx) = make_float2(a0 * 0.25f, a1 * 0.25f);
    } else {
        *reinterpret_cast<float2*>(g_x + idx)   = make_float2(n0, n1);
        *reinterpret_cast<float2*>(g_acc + idx) = make_float2(a0, a1);
        g_xh[idx / 2] = __floats2bfloat162_rn(n0, n1);
    }
}

// ---------------- launch ----------------
// Inputs in dict/insertion order:
//   d_in[0]=pois_embs, d_in[1]=up_rows, d_in[2]=up_cols, d_in[3]=up_vals,
//   d_in[4]=pu_rows,   d_in[5]=pu_cols, d_in[6]=pu_vals
extern "C" void kernel_launch(void* const* d_in, const int* in_sizes, int n_in,
                              void* d_out, int out_size) {
    const float* pois    = (const float*)d_in[0];
    const int*   up_rows = (const int*)  d_in[1];
    const int*   up_cols = (const int*)  d_in[2];
    const float* up_vals = (const float*)d_in[3];
    const int*   pu_rows = (const int*)  d_in[4];
    const int*   pu_cols = (const int*)  d_in[5];
    const float* pu_vals = (const float*)d_in[6];
    float* out = (float*)d_out;

    float *px, *pacc;
    int *pup_ptr, *pup_off, *ppu_ptr, *ppu_off;
    cudaGetSymbolAddress((void**)&px,      g_x);
    cudaGetSymbolAddress((void**)&pacc,    g_acc);
    cudaGetSymbolAddress((void**)&pup_ptr, g_up_ptr);
    cudaGetSymbolAddress((void**)&pup_off, g_up_off);
    cudaGetSymbolAddress((void**)&ppu_ptr, g_pu_ptr);
    cudaGetSymbolAddress((void**)&ppu_off, g_pu_off);

    // per-layer dropout keys: fold_in(key(42), l) = threefry((0,42),(0,l))
    uint32_t lk0[3], lk1[3];
    for (int l = 0; l < 3; ++l)
        tf2x32(0u, 42u, 0u, (uint32_t)l, lk0[l], lk1[l]);

    const int B = 256;
    const int NB_U = (NU + 1023) / 1024;   // 49
    const int NB_P = (NP + 1023) / 1024;   // 196

    // ---- CSR build (once per call, reused by all 3 layers) ----
    zero_cnt_kernel<<<(NP + 1 + B - 1) / B, B>>>();
    hist_kernel<<<(NNZE / 4 + B - 1) / B, B>>>((const int4*)up_rows,
                                               (const int4*)pu_rows);
    scan1_kernel<<<NB_U, 1024>>>(pup_ptr, pup_off, NU);
    scan2_kernel<<<1, 256>>>(NB_U, pup_ptr + NU);
    scan3_kernel<<<NB_U, 1024>>>(pup_ptr, pup_off, NU);
    scan1_kernel<<<NB_P, 1024>>>(ppu_ptr, ppu_off, NP);
    scan2_kernel<<<1, 256>>>(NB_P, ppu_ptr + NP);
    scan3_kernel<<<NB_P, 1024>>>(ppu_ptr, ppu_off, NP);
    scatter_kernel<<<(NNZE / 4 + B - 1) / B, B>>>(
        (const int4*)up_rows, (const int4*)up_cols, (const float4*)up_vals,
        (const int4*)pu_rows, (const int4*)pu_cols, (const float4*)pu_vals);

    // bf16 mirror of layer-0 x (= pois)
    cvt_kernel<<<(NTOT / 4 + B - 1) / B, B>>>((const float4*)pois);

    // ---- 3 layers ----
    for (int l = 0; l < 3; ++l) {
        const float* xcur = (l == 0) ? pois : px;
        const float* acur = (l == 0) ? pois : pacc;
        up_mask_kernel<<<UP_BLOCKS + MASK_BLOCKS, B>>>(lk0[l], lk1[l]);
        spmm_pu_fused_kernel<<<PU_BLOCKS, B>>>(xcur, acur, l == 2, out);
    }
}

// round 8
// speedup vs baseline: 1.0619x; 1.0619x over previous
#include <cuda_runtime.h>
#include <cuda_bf16.h>
#include <cstdint>

#define NP   200000
#define NU   50000
#define NNZE 2000000
#define DIM  64
#define NTOT (NP*DIM)      /* 12,800,000 */
#define MSGN (NU*DIM)      /*  3,200,000 */

#define UP_BLOCKS   ((NU * 32) / 256)    /* 6250  */
#define MASK_BLOCKS ((NTOT / 256) / 8)   /* 6250: 8 warps/block, 256 elems/warp */
#define PU_BLOCKS   ((NP * 32) / 256)    /* 25000 */
#define MASK_WORDS  (NTOT / 32)          /* 400000 */

__device__ __align__(16) float g_x[NTOT];
__device__ __align__(16) float g_acc[NTOT];
__device__ __align__(16) __nv_bfloat162 g_xh[NTOT / 2];    // bf16 mirror of x (gather operand)
__device__ __align__(16) __nv_bfloat162 g_msgh[MSGN / 2];  // bf16 msg (gather operand)
__device__ uint32_t g_mask[MASK_WORDS];                    // packed drop bits, per layer

// CSR scratch
__device__ int  g_up_ptr[NU + 1];
__device__ int  g_up_off[NU];
__device__ int2 g_up_cv[NNZE];     // packed (col, val-bits), row-grouped
__device__ int  g_pu_ptr[NP + 1];
__device__ int  g_pu_off[NP];
__device__ int2 g_pu_cv[NNZE];
__device__ int  g_bsum[256];

// ---------------- threefry2x32 (exact JAX semantics) ----------------
__host__ __device__ __forceinline__ uint32_t rotl32(uint32_t x, int d) {
    return (x << d) | (x >> (32 - d));
}

__host__ __device__ __forceinline__ void tf2x32(uint32_t k0, uint32_t k1,
                                                uint32_t x0, uint32_t x1,
                                                uint32_t &o0, uint32_t &o1) {
    uint32_t ks2 = k0 ^ k1 ^ 0x1BD11BDAu;
    x0 += k0; x1 += k1;
#define TFR(r) { x0 += x1; x1 = rotl32(x1, (r)); x1 ^= x0; }
    TFR(13) TFR(15) TFR(26) TFR(6)
    x0 += k1;  x1 += ks2 + 1u;
    TFR(17) TFR(29) TFR(16) TFR(24)
    x0 += ks2; x1 += k0 + 2u;
    TFR(13) TFR(15) TFR(26) TFR(6)
    x0 += k0;  x1 += k1 + 3u;
    TFR(17) TFR(29) TFR(16) TFR(24)
    x0 += k1;  x1 += ks2 + 4u;
    TFR(13) TFR(15) TFR(26) TFR(6)
    x0 += ks2; x1 += k0 + 5u;
#undef TFR
    o0 = x0; o1 = x1;
}

// partitionable threefry draw for element e (counter (0, e)), 32-bit: out0 ^ out1
__device__ __forceinline__ uint32_t tf_bits(uint32_t k0, uint32_t k1, uint32_t e) {
    uint32_t o0, o1;
    tf2x32(k0, k1, 0u, e, o0, o1);
    return o0 ^ o1;
}

// ---------------- CSR build ----------------
__global__ void zero_cnt_kernel() {
    int i = blockIdx.x * blockDim.x + threadIdx.x;
    if (i <= NU) g_up_ptr[i] = 0;
    if (i <= NP) g_pu_ptr[i] = 0;
}

__global__ void hist_kernel(const int4* __restrict__ up_rows,
                            const int4* __restrict__ pu_rows) {
    int e = blockIdx.x * blockDim.x + threadIdx.x;
    if (e >= NNZE / 4) return;
    int4 a = __ldg(up_rows + e);
    atomicAdd(&g_up_ptr[a.x], 1); atomicAdd(&g_up_ptr[a.y], 1);
    atomicAdd(&g_up_ptr[a.z], 1); atomicAdd(&g_up_ptr[a.w], 1);
    int4 b = __ldg(pu_rows + e);
    atomicAdd(&g_pu_ptr[b.x], 1); atomicAdd(&g_pu_ptr[b.y], 1);
    atomicAdd(&g_pu_ptr[b.z], 1); atomicAdd(&g_pu_ptr[b.w], 1);
}

// pass 1: per-block (1024) exclusive scan; excl -> off, block total -> g_bsum
__global__ void scan1_kernel(const int* __restrict__ cnt, int* __restrict__ excl,
                             int n) {
    __shared__ int ws[32];
    int t = threadIdx.x;
    int i = blockIdx.x * 1024 + t;
    int v = (i < n) ? cnt[i] : 0;
    int x = v;
#pragma unroll
    for (int d = 1; d < 32; d <<= 1) {
        int u = __shfl_up_sync(~0u, x, d);
        if ((t & 31) >= d) x += u;
    }
    if ((t & 31) == 31) ws[t >> 5] = x;
    __syncthreads();
    if (t < 32) {
        int w = ws[t];
#pragma unroll
        for (int d = 1; d < 32; d <<= 1) {
            int u = __shfl_up_sync(~0u, w, d);
            if (t >= d) w += u;
        }
        ws[t] = w;
    }
    __syncthreads();
    int base = (t >= 32) ? ws[(t >> 5) - 1] : 0;
    int incl = x + base;
    if (i < n) excl[i] = incl - v;
    if (t == 1023) g_bsum[blockIdx.x] = incl;
}

// pass 2: exclusive scan of <=256 block sums in place; total -> ptr[n]
__global__ void scan2_kernel(int nb, int* __restrict__ ptr_n) {
    __shared__ int ws[8];
    int t = threadIdx.x;       // 256 threads
    int v = (t < nb) ? g_bsum[t] : 0;
    int x = v;
#pragma unroll
    for (int d = 1; d < 32; d <<= 1) {
        int u = __shfl_up_sync(~0u, x, d);
        if ((t & 31) >= d) x += u;
    }
    if ((t & 31) == 31) ws[t >> 5] = x;
    __syncthreads();
    if (t < 8) {
        int w = ws[t];
#pragma unroll
        for (int d = 1; d < 8; d <<= 1) {
            int u = __shfl_up_sync(0xffu, w, d);
            if (t >= d) w += u;
        }
        ws[t] = w;
    }
    __syncthreads();
    int base = (t >= 32) ? ws[(t >> 5) - 1] : 0;
    int incl = x + base;
    if (t < nb) g_bsum[t] = incl - v;
    if (t == nb - 1) *ptr_n = incl;
}

// pass 3: add block offset; write both ptr and off
__global__ void scan3_kernel(int* __restrict__ ptr, int* __restrict__ off, int n) {
    int i = blockIdx.x * 1024 + threadIdx.x;
    if (i < n) {
        int v = off[i] + g_bsum[blockIdx.x];
        ptr[i] = v;
        off[i] = v;
    }
}

__global__ void scatter_kernel(const int4* __restrict__ up_rows,
                               const int4* __restrict__ up_cols,
                               const float4* __restrict__ up_vals,
                               const int4* __restrict__ pu_rows,
                               const int4* __restrict__ pu_cols,
                               const float4* __restrict__ pu_vals) {
    int e = blockIdx.x * blockDim.x + threadIdx.x;
    if (e >= NNZE / 4) return;
    {
        int4 r = __ldg(up_rows + e);
        int4 c = __ldg(up_cols + e);
        float4 v = __ldg(up_vals + e);
        g_up_cv[atomicAdd(&g_up_off[r.x], 1)] = make_int2(c.x, __float_as_int(v.x));
        g_up_cv[atomicAdd(&g_up_off[r.y], 1)] = make_int2(c.y, __float_as_int(v.y));
        g_up_cv[atomicAdd(&g_up_off[r.z], 1)] = make_int2(c.z, __float_as_int(v.z));
        g_up_cv[atomicAdd(&g_up_off[r.w], 1)] = make_int2(c.w, __float_as_int(v.w));
    }
    {
        int4 r = __ldg(pu_rows + e);
        int4 c = __ldg(pu_cols + e);
        float4 v = __ldg(pu_vals + e);
        g_pu_cv[atomicAdd(&g_pu_off[r.x], 1)] = make_int2(c.x, __float_as_int(v.x));
        g_pu_cv[atomicAdd(&g_pu_off[r.y], 1)] = make_int2(c.y, __float_as_int(v.y));
        g_pu_cv[atomicAdd(&g_pu_off[r.z], 1)] = make_int2(c.z, __float_as_int(v.z));
        g_pu_cv[atomicAdd(&g_pu_off[r.w], 1)] = make_int2(c.w, __float_as_int(v.w));
    }
}

// ---------------- fp32 -> bf16 mirror (layer 0 only) ----------------
__global__ void cvt_kernel(const float4* __restrict__ src) {
    int i = blockIdx.x * blockDim.x + threadIdx.x;   // one float4 -> two bf162
    if (i >= NTOT / 4) return;
    float4 v = src[i];
    g_xh[2 * i]     = __floats2bfloat162_rn(v.x, v.y);
    g_xh[2 * i + 1] = __floats2bfloat162_rn(v.z, v.w);
}

// ---------------- UP SpMM + mask generation (one launch, split grid) --------
// blocks [0, UP_BLOCKS): warp-per-U-row SpMM (broadcast cv loads, MLP-friendly).
// blocks [UP_BLOCKS, UP_BLOCKS+MASK_BLOCKS): packed dropout masks for layer l.
__global__ void up_mask_kernel(uint32_t k0, uint32_t k1) {
    int lane = threadIdx.x & 31;
    if (blockIdx.x < UP_BLOCKS) {
        int w = (blockIdx.x * 256 + threadIdx.x) >> 5;   // < NU by construction
        int s = __ldg(g_up_ptr + w), e = __ldg(g_up_ptr + w + 1);
        float accx = 0.f, accy = 0.f;
        for (int j = s; j < e; ++j) {
            int2 cv = __ldg(g_up_cv + j);                // same addr all lanes: broadcast
            float v = __int_as_float(cv.y);
            float2 xv = __bfloat1622float2(g_xh[(size_t)cv.x * (DIM / 2) + lane]);
            accx += v * xv.x;
            accy += v * xv.y;
        }
        g_msgh[(size_t)w * (DIM / 2) + lane] = __floats2bfloat162_rn(accx, accy);
    } else {
        // maskgen: warp wm covers elements [wm*256, wm*256+256)
        int wm = ((blockIdx.x - UP_BLOCKS) * 256 + threadIdx.x) >> 5;
        uint32_t ebase = (uint32_t)wm * 256u + (uint32_t)lane;
#pragma unroll
        for (int i = 0; i < 8; ++i) {
            uint32_t bits = tf_bits(k0, k1, ebase + (uint32_t)(i * 32));
            uint32_t bal = __ballot_sync(~0u, bits >> 31);   // 1 = drop
            if (lane == 0) g_mask[wm * 8 + i] = bal;
        }
    }
}

// ---------------- PU SpMM fused with residual + dropout + acc ----------------
__global__ void spmm_pu_fused_kernel(const float* __restrict__ x_in,
                                     const float* __restrict__ acc_in,
                                     int last, float* __restrict__ out) {
    int w = (blockIdx.x * 256 + threadIdx.x) >> 5;       // < NP by construction
    int lane = threadIdx.x & 31;
    int s = __ldg(g_pu_ptr + w), e = __ldg(g_pu_ptr + w + 1);
    float accx = 0.f, accy = 0.f;
    for (int j = s; j < e; ++j) {
        int2 cv = __ldg(g_pu_cv + j);                    // broadcast load
        float v = __int_as_float(cv.y);
        float2 xv = __bfloat1622float2(g_msgh[(size_t)cv.x * (DIM / 2) + lane]);
        accx += v * xv.x;
        accy += v * xv.y;
    }
    size_t idx = (size_t)w * DIM + lane * 2;

    uint32_t word = __ldg(&g_mask[2 * w + (lane >> 4)]); // broadcast: 2 words/warp
    int sh = (lane & 15) * 2;

    float2 xv = *reinterpret_cast<const float2*>(x_in + idx);
    float2 av = *reinterpret_cast<const float2*>(acc_in + idx);
    float n0 = ((word >> sh)       & 1u) ? 0.f : 2.f * (accx + xv.x);
    float n1 = ((word >> (sh + 1)) & 1u) ? 0.f : 2.f * (accy + xv.y);
    float a0 = av.x + n0;
    float a1 = av.y + n1;

    if (last) {
        *reinterpret_cast<float2*>(out + idx) = make_float2(a0 * 0.25f, a1 * 0.25f);
    } else {
        *reinterpret_cast<float2*>(g_x + idx)   = make_float2(n0, n1);
        *reinterpret_cast<float2*>(g_acc + idx) = make_float2(a0, a1);
        g_xh[idx / 2] = __floats2bfloat162_rn(n0, n1);
    }
}

// ---------------- launch ----------------
// Inputs in dict/insertion order:
//   d_in[0]=pois_embs, d_in[1]=up_rows, d_in[2]=up_cols, d_in[3]=up_vals,
//   d_in[4]=pu_rows,   d_in[5]=pu_cols, d_in[6]=pu_vals
extern "C" void kernel_launch(void* const* d_in, const int* in_sizes, int n_in,
                              void* d_out, int out_size) {
    const float* pois    = (const float*)d_in[0];
    const int*   up_rows = (const int*)  d_in[1];
    const int*   up_cols = (const int*)  d_in[2];
    const float* up_vals = (const float*)d_in[3];
    const int*   pu_rows = (const int*)  d_in[4];
    const int*   pu_cols = (const int*)  d_in[5];
    const float* pu_vals = (const float*)d_in[6];
    float* out = (float*)d_out;

    float *px, *pacc;
    int *pup_ptr, *pup_off, *ppu_ptr, *ppu_off;
    cudaGetSymbolAddress((void**)&px,      g_x);
    cudaGetSymbolAddress((void**)&pacc,    g_acc);
    cudaGetSymbolAddress((void**)&pup_ptr, g_up_ptr);
    cudaGetSymbolAddress((void**)&pup_off, g_up_off);
    cudaGetSymbolAddress((void**)&ppu_ptr, g_pu_ptr);
    cudaGetSymbolAddress((void**)&ppu_off, g_pu_off);

    // per-layer dropout keys: fold_in(key(42), l) = threefry((0,42),(0,l))
    uint32_t lk0[3], lk1[3];
    for (int l = 0; l < 3; ++l)
        tf2x32(0u, 42u, 0u, (uint32_t)l, lk0[l], lk1[l]);

    const int B = 256;
    const int NB_U = (NU + 1023) / 1024;   // 49
    const int NB_P = (NP + 1023) / 1024;   // 196

    // ---- CSR build (once per call, reused by all 3 layers) ----
    zero_cnt_kernel<<<(NP + 1 + B - 1) / B, B>>>();
    hist_kernel<<<(NNZE / 4 + B - 1) / B, B>>>((const int4*)up_rows,
                                               (const int4*)pu_rows);
    scan1_kernel<<<NB_U, 1024>>>(pup_ptr, pup_off, NU);
    scan2_kernel<<<1, 256>>>(NB_U, pup_ptr + NU);
    scan3_kernel<<<NB_U, 1024>>>(pup_ptr, pup_off, NU);
    scan1_kernel<<<NB_P, 1024>>>(ppu_ptr, ppu_off, NP);
    scan2_kernel<<<1, 256>>>(NB_P, ppu_ptr + NP);
    scan3_kernel<<<NB_P, 1024>>>(ppu_ptr, ppu_off, NP);
    scatter_kernel<<<(NNZE / 4 + B - 1) / B, B>>>(
        (const int4*)up_rows, (const int4*)up_cols, (const float4*)up_vals,
        (const int4*)pu_rows, (const int4*)pu_cols, (const float4*)pu_vals);

    // bf16 mirror of layer-0 x (= pois)
    cvt_kernel<<<(NTOT / 4 + B - 1) / B, B>>>((const float4*)pois);

    // ---- 3 layers ----
    for (int l = 0; l < 3; ++l) {
        const float* xcur = (l == 0) ? pois : px;
        const float* acur = (l == 0) ? pois : pacc;
        up_mask_kernel<<<UP_BLOCKS + MASK_BLOCKS, B>>>(lk0[l], lk1[l]);
        spmm_pu_fused_kernel<<<PU_BLOCKS, B>>>(xcur, acur, l == 2, out);
    }
}

// round 9
// speedup vs baseline: 1.1426x; 1.0760x over previous
#include <cuda_runtime.h>
#include <cuda_bf16.h>
#include <cstdint>

#define NP   200000
#define NU   50000
#define NNZE 2000000
#define DIM  64
#define NTOT (NP*DIM)      /* 12,800,000 */
#define MSGN (NU*DIM)      /*  3,200,000 */

#define NB_U ((NU + 1023) / 1024)   /* 49  */
#define NB_P ((NP + 1023) / 1024)   /* 196 */

__device__ __align__(16) float g_x[NTOT];
__device__ __align__(16) float g_acc[NTOT];
__device__ __align__(16) __nv_bfloat162 g_xh[NTOT / 2];    // bf16 mirror of x (gather operand)
__device__ __align__(16) __nv_bfloat162 g_msgh[MSGN / 2];  // bf16 msg (gather operand)

// CSR scratch
__device__ int  g_up_ptr[NU + 1];
__device__ int  g_up_off[NU];
__device__ int2 g_up_cv[NNZE];     // packed (col, val-bits), row-grouped
__device__ int  g_pu_ptr[NP + 1];
__device__ int  g_pu_off[NP];
__device__ int2 g_pu_cv[NNZE];
__device__ int  g_bsum_u[64];
__device__ int  g_bsum_p[256];

// ---------------- threefry2x32 (exact JAX semantics) ----------------
__host__ __device__ __forceinline__ uint32_t rotl32(uint32_t x, int d) {
    return (x << d) | (x >> (32 - d));
}

__host__ __device__ __forceinline__ void tf2x32(uint32_t k0, uint32_t k1,
                                                uint32_t x0, uint32_t x1,
                                                uint32_t &o0, uint32_t &o1) {
    uint32_t ks2 = k0 ^ k1 ^ 0x1BD11BDAu;
    x0 += k0; x1 += k1;
#define TFR(r) { x0 += x1; x1 = rotl32(x1, (r)); x1 ^= x0; }
    TFR(13) TFR(15) TFR(26) TFR(6)
    x0 += k1;  x1 += ks2 + 1u;
    TFR(17) TFR(29) TFR(16) TFR(24)
    x0 += ks2; x1 += k0 + 2u;
    TFR(13) TFR(15) TFR(26) TFR(6)
    x0 += k0;  x1 += k1 + 3u;
    TFR(17) TFR(29) TFR(16) TFR(24)
    x0 += k1;  x1 += ks2 + 4u;
    TFR(13) TFR(15) TFR(26) TFR(6)
    x0 += ks2; x1 += k0 + 5u;
#undef TFR
    o0 = x0; o1 = x1;
}

// partitionable threefry draw for element e (counter (0, e)), 32-bit: out0 ^ out1
__device__ __forceinline__ uint32_t tf_bits(uint32_t k0, uint32_t k1, uint32_t e) {
    uint32_t o0, o1;
    tf2x32(k0, k1, 0u, e, o0, o1);
    return o0 ^ o1;
}

__device__ __forceinline__ float dropv(uint32_t bits, float s) {
    return (bits & 0x80000000u) ? 0.f : 2.f * s;   // keep iff MSB==0, scale 1/keep=2
}

// raw bf162 gather through the RO path
__device__ __forceinline__ float2 gather_bf2(const __nv_bfloat162* p, size_t idx) {
    uint32_t raw = __ldg(reinterpret_cast<const uint32_t*>(p) + idx);
    __nv_bfloat162 h = *reinterpret_cast<__nv_bfloat162*>(&raw);
    return __bfloat1622float2(h);
}

// ---------------- CSR build ----------------
__global__ void zero_cnt_kernel() {
    int i = blockIdx.x * blockDim.x + threadIdx.x;
    if (i <= NU) g_up_ptr[i] = 0;
    if (i <= NP) g_pu_ptr[i] = 0;
}

__global__ void hist_kernel(const int* __restrict__ up_rows,
                            const int* __restrict__ pu_rows) {
    int e = blockIdx.x * blockDim.x + threadIdx.x;
    if (e >= NNZE) return;
    atomicAdd(&g_up_ptr[__ldg(up_rows + e)], 1);
    atomicAdd(&g_pu_ptr[__ldg(pu_rows + e)], 1);
}

// merged pass 1: blocks [0,NB_U) scan UP counts, [NB_U,NB_U+NB_P) scan PU counts
__global__ void scan1_kernel() {
    __shared__ int ws[32];
    int t = threadIdx.x;
    bool isU = blockIdx.x < NB_U;
    int lb = isU ? blockIdx.x : blockIdx.x - NB_U;
    int n  = isU ? NU : NP;
    const int* cnt = isU ? g_up_ptr : g_pu_ptr;
    int* excl      = isU ? g_up_off : g_pu_off;
    int* bsum      = isU ? g_bsum_u : g_bsum_p;

    int i = lb * 1024 + t;
    int v = (i < n) ? cnt[i] : 0;
    int x = v;
#pragma unroll
    for (int d = 1; d < 32; d <<= 1) {
        int u = __shfl_up_sync(~0u, x, d);
        if ((t & 31) >= d) x += u;
    }
    if ((t & 31) == 31) ws[t >> 5] = x;
    __syncthreads();
    if (t < 32) {
        int w = ws[t];
#pragma unroll
        for (int d = 1; d < 32; d <<= 1) {
            int u = __shfl_up_sync(~0u, w, d);
            if (t >= d) w += u;
        }
        ws[t] = w;
    }
    __syncthreads();
    int base = (t >= 32) ? ws[(t >> 5) - 1] : 0;
    int incl = x + base;
    if (i < n) excl[i] = incl - v;
    if (t == 1023) bsum[lb] = incl;
}

// merged pass 2: block 0 scans UP block sums, block 1 scans PU block sums
__global__ void scan2_kernel() {
    __shared__ int ws[8];
    bool isU = blockIdx.x == 0;
    int nb   = isU ? NB_U : NB_P;
    int* bsum = isU ? g_bsum_u : g_bsum_p;
    int* ptr_n = isU ? &g_up_ptr[NU] : &g_pu_ptr[NP];

    int t = threadIdx.x;       // 256 threads
    int v = (t < nb) ? bsum[t] : 0;
    int x = v;
#pragma unroll
    for (int d = 1; d < 32; d <<= 1) {
        int u = __shfl_up_sync(~0u, x, d);
        if ((t & 31) >= d) x += u;
    }
    if ((t & 31) == 31) ws[t >> 5] = x;
    __syncthreads();
    if (t < 8) {
        int w = ws[t];
#pragma unroll
        for (int d = 1; d < 8; d <<= 1) {
            int u = __shfl_up_sync(0xffu, w, d);
            if (t >= d) w += u;
        }
        ws[t] = w;
    }
    __syncthreads();
    int base = (t >= 32) ? ws[(t >> 5) - 1] : 0;
    int incl = x + base;
    if (t < nb) bsum[t] = incl - v;
    if (t == nb - 1) *ptr_n = incl;
}

// merged pass 3: add block offset; write both ptr and off
__global__ void scan3_kernel() {
    bool isU = blockIdx.x < NB_U;
    int lb = isU ? blockIdx.x : blockIdx.x - NB_U;
    int n  = isU ? NU : NP;
    int* ptr = isU ? g_up_ptr : g_pu_ptr;
    int* off = isU ? g_up_off : g_pu_off;
    const int* bsum = isU ? g_bsum_u : g_bsum_p;

    int i = lb * 1024 + threadIdx.x;
    if (i < n) {
        int v = off[i] + bsum[lb];
        ptr[i] = v;
        off[i] = v;
    }
}

__global__ void scatter_kernel(const int* __restrict__ up_rows,
                               const int* __restrict__ up_cols,
                               const float* __restrict__ up_vals,
                               const int* __restrict__ pu_rows,
                               const int* __restrict__ pu_cols,
                               const float* __restrict__ pu_vals) {
    int e = blockIdx.x * blockDim.x + threadIdx.x;
    if (e >= NNZE) return;
    {
        int r = __ldg(up_rows + e);
        int p = atomicAdd(&g_up_off[r], 1);
        g_up_cv[p] = make_int2(__ldg(up_cols + e), __float_as_int(__ldg(up_vals + e)));
    }
    {
        int r = __ldg(pu_rows + e);
        int p = atomicAdd(&g_pu_off[r], 1);
        g_pu_cv[p] = make_int2(__ldg(pu_cols + e), __float_as_int(__ldg(pu_vals + e)));
    }
}

// ---------------- fp32 -> bf16 mirror (layer 0 only) ----------------
__global__ void cvt_kernel(const float4* __restrict__ src) {
    int i = blockIdx.x * blockDim.x + threadIdx.x;   // one float4 -> two bf162
    if (i >= NTOT / 4) return;
    float4 v = src[i];
    g_xh[2 * i]     = __floats2bfloat162_rn(v.x, v.y);
    g_xh[2 * i + 1] = __floats2bfloat162_rn(v.z, v.w);
}

// ---------------- UP SpMM: warp per U-row, 4x pipelined gather loop ----------
__global__ void spmm_up_kernel() {
    int w = (blockIdx.x * 256 + threadIdx.x) >> 5;       // < NU by construction
    int lane = threadIdx.x & 31;
    int s = __ldg(g_up_ptr + w), e = __ldg(g_up_ptr + w + 1);
    float accx = 0.f, accy = 0.f;
    int j = s;
    for (; j + 4 <= e; j += 4) {
        int2 c0 = __ldg(g_up_cv + j);
        int2 c1 = __ldg(g_up_cv + j + 1);
        int2 c2 = __ldg(g_up_cv + j + 2);
        int2 c3 = __ldg(g_up_cv + j + 3);
        float2 x0 = gather_bf2(g_xh, (size_t)c0.x * (DIM / 2) + lane);
        float2 x1 = gather_bf2(g_xh, (size_t)c1.x * (DIM / 2) + lane);
        float2 x2 = gather_bf2(g_xh, (size_t)c2.x * (DIM / 2) + lane);
        float2 x3 = gather_bf2(g_xh, (size_t)c3.x * (DIM / 2) + lane);
        accx += __int_as_float(c0.y) * x0.x; accy += __int_as_float(c0.y) * x0.y;
        accx += __int_as_float(c1.y) * x1.x; accy += __int_as_float(c1.y) * x1.y;
        accx += __int_as_float(c2.y) * x2.x; accy += __int_as_float(c2.y) * x2.y;
        accx += __int_as_float(c3.y) * x3.x; accy += __int_as_float(c3.y) * x3.y;
    }
    for (; j < e; ++j) {
        int2 cv = __ldg(g_up_cv + j);
        float v = __int_as_float(cv.y);
        float2 xv = gather_bf2(g_xh, (size_t)cv.x * (DIM / 2) + lane);
        accx += v * xv.x;
        accy += v * xv.y;
    }
    g_msgh[(size_t)w * (DIM / 2) + lane] = __floats2bfloat162_rn(accx, accy);
}

// ---------------- PU SpMM fused with residual + dropout + acc ----------------
__global__ void spmm_pu_fused_kernel(const float* __restrict__ x_in,
                                     const float* __restrict__ acc_in,
                                     uint32_t k0, uint32_t k1, int last,
                                     float* __restrict__ out) {
    int w = (blockIdx.x * 256 + threadIdx.x) >> 5;       // < NP by construction
    int lane = threadIdx.x & 31;
    int s = __ldg(g_pu_ptr + w), e = __ldg(g_pu_ptr + w + 1);
    float accx = 0.f, accy = 0.f;
    int j = s;
    for (; j + 4 <= e; j += 4) {
        int2 c0 = __ldg(g_pu_cv + j);
        int2 c1 = __ldg(g_pu_cv + j + 1);
        int2 c2 = __ldg(g_pu_cv + j + 2);
        int2 c3 = __ldg(g_pu_cv + j + 3);
        float2 x0 = gather_bf2(g_msgh, (size_t)c0.x * (DIM / 2) + lane);
        float2 x1 = gather_bf2(g_msgh, (size_t)c1.x * (DIM / 2) + lane);
        float2 x2 = gather_bf2(g_msgh, (size_t)c2.x * (DIM / 2) + lane);
        float2 x3 = gather_bf2(g_msgh, (size_t)c3.x * (DIM / 2) + lane);
        accx += __int_as_float(c0.y) * x0.x; accy += __int_as_float(c0.y) * x0.y;
        accx += __int_as_float(c1.y) * x1.x; accy += __int_as_float(c1.y) * x1.y;
        accx += __int_as_float(c2.y) * x2.x; accy += __int_as_float(c2.y) * x2.y;
        accx += __int_as_float(c3.y) * x3.x; accy += __int_as_float(c3.y) * x3.y;
    }
    for (; j < e; ++j) {
        int2 cv = __ldg(g_pu_cv + j);
        float v = __int_as_float(cv.y);
        float2 xv = gather_bf2(g_msgh, (size_t)cv.x * (DIM / 2) + lane);
        accx += v * xv.x;
        accy += v * xv.y;
    }
    size_t idx = (size_t)w * DIM + lane * 2;
    uint32_t e0 = (uint32_t)idx;
    uint32_t b0 = tf_bits(k0, k1, e0);
    uint32_t b1 = tf_bits(k0, k1, e0 + 1u);

    float2 xv = *reinterpret_cast<const float2*>(x_in + idx);
    float2 av = *reinterpret_cast<const float2*>(acc_in + idx);
    float n0 = dropv(b0, accx + xv.x);
    float n1 = dropv(b1, accy + xv.y);
    float a0 = av.x + n0;
    float a1 = av.y + n1;

    if (last) {
        *reinterpret_cast<float2*>(out + idx) = make_float2(a0 * 0.25f, a1 * 0.25f);
    } else {
        *reinterpret_cast<float2*>(g_x + idx)   = make_float2(n0, n1);
        *reinterpret_cast<float2*>(g_acc + idx) = make_float2(a0, a1);
        g_xh[idx / 2] = __floats2bfloat162_rn(n0, n1);
    }
}

// ---------------- launch ----------------
// Inputs in dict/insertion order:
//   d_in[0]=pois_embs, d_in[1]=up_rows, d_in[2]=up_cols, d_in[3]=up_vals,
//   d_in[4]=pu_rows,   d_in[5]=pu_cols, d_in[6]=pu_vals
extern "C" void kernel_launch(void* const* d_in, const int* in_sizes, int n_in,
                              void* d_out, int out_size) {
    const float* pois    = (const float*)d_in[0];
    const int*   up_rows = (const int*)  d_in[1];
    const int*   up_cols = (const int*)  d_in[2];
    const float* up_vals = (const float*)d_in[3];
    const int*   pu_rows = (const int*)  d_in[4];
    const int*   pu_cols = (const int*)  d_in[5];
    const float* pu_vals = (const float*)d_in[6];
    float* out = (float*)d_out;

    float *px, *pacc;
    cudaGetSymbolAddress((void**)&px,   g_x);
    cudaGetSymbolAddress((void**)&pacc, g_acc);

    // per-layer dropout keys: fold_in(key(42), l) = threefry((0,42),(0,l))
    uint32_t lk0[3], lk1[3];
    for (int l = 0; l < 3; ++l)
        tf2x32(0u, 42u, 0u, (uint32_t)l, lk0[l], lk1[l]);

    const int B = 256;

    // ---- CSR build (once per call, reused by all 3 layers) ----
    zero_cnt_kernel<<<(NP + 1 + B - 1) / B, B>>>();
    hist_kernel<<<(NNZE + B - 1) / B, B>>>(up_rows, pu_rows);
    scan1_kernel<<<NB_U + NB_P, 1024>>>();
    scan2_kernel<<<2, 256>>>();
    scan3_kernel<<<NB_U + NB_P, 1024>>>();
    scatter_kernel<<<(NNZE + B - 1) / B, B>>>(up_rows, up_cols, up_vals,
                                              pu_rows, pu_cols, pu_vals);

    // bf16 mirror of layer-0 x (= pois)
    cvt_kernel<<<(NTOT / 4 + B - 1) / B, B>>>((const float4*)pois);

    // ---- 3 layers ----
    for (int l = 0; l < 3; ++l) {
        const float* xcur = (l == 0) ? pois : px;
        const float* acur = (l == 0) ? pois : pacc;
        spmm_up_kernel<<<(NU * 32) / B, B>>>();
        spmm_pu_fused_kernel<<<(NP * 32) / B, B>>>(xcur, acur,
                                                   lk0[l], lk1[l],
                                                   l == 2, out);
    }
}

// round 10
// speedup vs baseline: 1.1951x; 1.0459x over previous
#include <cuda_runtime.h>
#include <cuda_bf16.h>
#include <cstdint>

#define NP   200000
#define NU   50000
#define NNZE 2000000
#define DIM  64
#define NTOT (NP*DIM)      /* 12,800,000 */
#define MSGN (NU*DIM)      /*  3,200,000 */

__device__ __align__(16) float g_xa[NTOT];                 // layer-1 x (and ping)
__device__ __align__(16) float g_xb[NTOT];                 // layer-2 x (pong)
__device__ __align__(16) __nv_bfloat162 g_xh[NTOT / 2];    // bf16 mirror of current x
__device__ __align__(16) __nv_bfloat162 g_msgh[MSGN / 2];  // bf16 msg (gather operand)

// CSR scratch
__device__ int  g_up_ptr[NU + 1];
__device__ int  g_up_off[NU];
__device__ int2 g_up_cv[NNZE];     // packed (col, val-bits), row-grouped
__device__ int  g_pu_ptr[NP + 1];
__device__ int  g_pu_off[NP];
__device__ int2 g_pu_cv[NNZE];
__device__ int  g_bsum[256];

// ---------------- threefry2x32 (exact JAX semantics) ----------------
__host__ __device__ __forceinline__ uint32_t rotl32(uint32_t x, int d) {
    return (x << d) | (x >> (32 - d));
}

__host__ __device__ __forceinline__ void tf2x32(uint32_t k0, uint32_t k1,
                                                uint32_t x0, uint32_t x1,
                                                uint32_t &o0, uint32_t &o1) {
    uint32_t ks2 = k0 ^ k1 ^ 0x1BD11BDAu;
    x0 += k0; x1 += k1;
#define TFR(r) { x0 += x1; x1 = rotl32(x1, (r)); x1 ^= x0; }
    TFR(13) TFR(15) TFR(26) TFR(6)
    x0 += k1;  x1 += ks2 + 1u;
    TFR(17) TFR(29) TFR(16) TFR(24)
    x0 += ks2; x1 += k0 + 2u;
    TFR(13) TFR(15) TFR(26) TFR(6)
    x0 += k0;  x1 += k1 + 3u;
    TFR(17) TFR(29) TFR(16) TFR(24)
    x0 += k1;  x1 += ks2 + 4u;
    TFR(13) TFR(15) TFR(26) TFR(6)
    x0 += ks2; x1 += k0 + 5u;
#undef TFR
    o0 = x0; o1 = x1;
}

// partitionable threefry draw for element e (counter (0, e)), 32-bit: out0 ^ out1
__device__ __forceinline__ uint32_t tf_bits(uint32_t k0, uint32_t k1, uint32_t e) {
    uint32_t o0, o1;
    tf2x32(k0, k1, 0u, e, o0, o1);
    return o0 ^ o1;
}

__device__ __forceinline__ float dropv(uint32_t bits, float s) {
    return (bits & 0x80000000u) ? 0.f : 2.f * s;   // keep iff MSB==0, scale 1/keep=2
}

// ---------------- CSR build ----------------
__global__ void zero_cnt_kernel() {
    int i = blockIdx.x * blockDim.x + threadIdx.x;
    if (i <= NU) g_up_ptr[i] = 0;
    if (i <= NP) g_pu_ptr[i] = 0;
}

__global__ void hist_kernel(const int* __restrict__ up_rows,
                            const int* __restrict__ pu_rows) {
    int e = blockIdx.x * blockDim.x + threadIdx.x;
    if (e >= NNZE) return;
    atomicAdd(&g_up_ptr[__ldg(up_rows + e)], 1);
    atomicAdd(&g_pu_ptr[__ldg(pu_rows + e)], 1);
}

// pass 1: per-block (1024) exclusive scan; excl -> off, block total -> g_bsum
__global__ void scan1_kernel(const int* __restrict__ cnt, int* __restrict__ excl,
                             int n) {
    __shared__ int ws[32];
    int t = threadIdx.x;
    int i = blockIdx.x * 1024 + t;
    int v = (i < n) ? cnt[i] : 0;
    int x = v;
#pragma unroll
    for (int d = 1; d < 32; d <<= 1) {
        int u = __shfl_up_sync(~0u, x, d);
        if ((t & 31) >= d) x += u;
    }
    if ((t & 31) == 31) ws[t >> 5] = x;
    __syncthreads();
    if (t < 32) {
        int w = ws[t];
#pragma unroll
        for (int d = 1; d < 32; d <<= 1) {
            int u = __shfl_up_sync(~0u, w, d);
            if (t >= d) w += u;
        }
        ws[t] = w;
    }
    __syncthreads();
    int base = (t >= 32) ? ws[(t >> 5) - 1] : 0;
    int incl = x + base;
    if (i < n) excl[i] = incl - v;
    if (t == 1023) g_bsum[blockIdx.x] = incl;
}

// pass 2: exclusive scan of <=256 block sums in place; total -> ptr[n]
__global__ void scan2_kernel(int nb, int* __restrict__ ptr_n) {
    __shared__ int ws[8];
    int t = threadIdx.x;       // 256 threads
    int v = (t < nb) ? g_bsum[t] : 0;
    int x = v;
#pragma unroll
    for (int d = 1; d < 32; d <<= 1) {
        int u = __shfl_up_sync(~0u, x, d);
        if ((t & 31) >= d) x += u;
    }
    if ((t & 31) == 31) ws[t >> 5] = x;
    __syncthreads();
    if (t < 8) {
        int w = ws[t];
#pragma unroll
        for (int d = 1; d < 8; d <<= 1) {
            int u = __shfl_up_sync(0xffu, w, d);
            if (t >= d) w += u;
        }
        ws[t] = w;
    }
    __syncthreads();
    int base = (t >= 32) ? ws[(t >> 5) - 1] : 0;
    int incl = x + base;
    if (t < nb) g_bsum[t] = incl - v;
    if (t == nb - 1) *ptr_n = incl;
}

// pass 3: add block offset; write both ptr and off
__global__ void scan3_kernel(int* __restrict__ ptr, int* __restrict__ off, int n) {
    int i = blockIdx.x * 1024 + threadIdx.x;
    if (i < n) {
        int v = off[i] + g_bsum[blockIdx.x];
        ptr[i] = v;
        off[i] = v;
    }
}

__global__ void scatter_kernel(const int* __restrict__ up_rows,
                               const int* __restrict__ up_cols,
                               const float* __restrict__ up_vals,
                               const int* __restrict__ pu_rows,
                               const int* __restrict__ pu_cols,
                               const float* __restrict__ pu_vals) {
    int e = blockIdx.x * blockDim.x + threadIdx.x;
    if (e >= NNZE) return;
    {
        int r = __ldg(up_rows + e);
        int p = atomicAdd(&g_up_off[r], 1);
        g_up_cv[p] = make_int2(__ldg(up_cols + e), __float_as_int(__ldg(up_vals + e)));
    }
    {
        int r = __ldg(pu_rows + e);
        int p = atomicAdd(&g_pu_off[r], 1);
        g_pu_cv[p] = make_int2(__ldg(pu_cols + e), __float_as_int(__ldg(pu_vals + e)));
    }
}

// ---------------- fp32 -> bf16 mirror (layer 0 only) ----------------
__global__ void cvt_kernel(const float4* __restrict__ src) {
    int i = blockIdx.x * blockDim.x + threadIdx.x;   // one float4 -> two bf162
    if (i >= NTOT / 4) return;
    float4 v = src[i];
    g_xh[2 * i]     = __floats2bfloat162_rn(v.x, v.y);
    g_xh[2 * i + 1] = __floats2bfloat162_rn(v.z, v.w);
}

// ---------------- UP SpMM: one warp per U-row; bf16 gather, fp32 accum ----
__global__ void spmm_up_kernel() {
    int w = (blockIdx.x * 256 + threadIdx.x) >> 5;       // < NU by construction
    int lane = threadIdx.x & 31;
    int s = __ldg(g_up_ptr + w), e = __ldg(g_up_ptr + w + 1);
    float accx = 0.f, accy = 0.f;
    for (int j = s; j < e; ++j) {
        int2 cv = __ldg(g_up_cv + j);                // same addr all lanes: broadcast
        float v = __int_as_float(cv.y);
        float2 xv = __bfloat1622float2(g_xh[(size_t)cv.x * (DIM / 2) + lane]);
        accx += v * xv.x;
        accy += v * xv.y;
    }
    g_msgh[(size_t)w * (DIM / 2) + lane] = __floats2bfloat162_rn(accx, accy);
}

// ---------------- PU SpMM fused with residual + dropout (+ final mean) ------
// last==0: x_next = drop(prop + x_in); write x_next (fp32 -> x_out, bf16 -> g_xh)
// last==1: out = 0.25*(pois + x1 + x_in + drop(prop + x_in))
__global__ void spmm_pu_fused_kernel(const float* __restrict__ x_in,
                                     float* __restrict__ x_out,
                                     const float* __restrict__ pois_in,
                                     const float* __restrict__ x1_in,
                                     uint32_t k0, uint32_t k1, int last,
                                     float* __restrict__ out) {
    int w = (blockIdx.x * 256 + threadIdx.x) >> 5;       // < NP by construction
    int lane = threadIdx.x & 31;
    int s = __ldg(g_pu_ptr + w), e = __ldg(g_pu_ptr + w + 1);
    float accx = 0.f, accy = 0.f;
    for (int j = s; j < e; ++j) {
        int2 cv = __ldg(g_pu_cv + j);                    // broadcast load
        float v = __int_as_float(cv.y);
        float2 xv = __bfloat1622float2(g_msgh[(size_t)cv.x * (DIM / 2) + lane]);
        accx += v * xv.x;
        accy += v * xv.y;
    }
    size_t idx = (size_t)w * DIM + lane * 2;
    uint32_t e0 = (uint32_t)idx;
    uint32_t b0 = tf_bits(k0, k1, e0);
    uint32_t b1 = tf_bits(k0, k1, e0 + 1u);

    float2 xv = *reinterpret_cast<const float2*>(x_in + idx);
    float n0 = dropv(b0, accx + xv.x);
    float n1 = dropv(b1, accy + xv.y);

    if (last) {
        float2 pv = *reinterpret_cast<const float2*>(pois_in + idx);
        float2 x1 = *reinterpret_cast<const float2*>(x1_in + idx);
        *reinterpret_cast<float2*>(out + idx) =
            make_float2((pv.x + x1.x + xv.x + n0) * 0.25f,
                        (pv.y + x1.y + xv.y + n1) * 0.25f);
    } else {
        *reinterpret_cast<float2*>(x_out + idx) = make_float2(n0, n1);
        g_xh[idx / 2] = __floats2bfloat162_rn(n0, n1);
    }
}

// ---------------- launch ----------------
// Inputs in dict/insertion order:
//   d_in[0]=pois_embs, d_in[1]=up_rows, d_in[2]=up_cols, d_in[3]=up_vals,
//   d_in[4]=pu_rows,   d_in[5]=pu_cols, d_in[6]=pu_vals
extern "C" void kernel_launch(void* const* d_in, const int* in_sizes, int n_in,
                              void* d_out, int out_size) {
    const float* pois    = (const float*)d_in[0];
    const int*   up_rows = (const int*)  d_in[1];
    const int*   up_cols = (const int*)  d_in[2];
    const float* up_vals = (const float*)d_in[3];
    const int*   pu_rows = (const int*)  d_in[4];
    const int*   pu_cols = (const int*)  d_in[5];
    const float* pu_vals = (const float*)d_in[6];
    float* out = (float*)d_out;

    float *pxa, *pxb;
    int *pup_ptr, *pup_off, *ppu_ptr, *ppu_off;
    cudaGetSymbolAddress((void**)&pxa,     g_xa);
    cudaGetSymbolAddress((void**)&pxb,     g_xb);
    cudaGetSymbolAddress((void**)&pup_ptr, g_up_ptr);
    cudaGetSymbolAddress((void**)&pup_off, g_up_off);
    cudaGetSymbolAddress((void**)&ppu_ptr, g_pu_ptr);
    cudaGetSymbolAddress((void**)&ppu_off, g_pu_off);

    // per-layer dropout keys: fold_in(key(42), l) = threefry((0,42),(0,l))
    uint32_t lk0[3], lk1[3];
    for (int l = 0; l < 3; ++l)
        tf2x32(0u, 42u, 0u, (uint32_t)l, lk0[l], lk1[l]);

    const int B = 256;
    const int NB_U = (NU + 1023) / 1024;   // 49
    const int NB_P = (NP + 1023) / 1024;   // 196

    // ---- CSR build (once per call, reused by all 3 layers) ----
    zero_cnt_kernel<<<(NP + 1 + B - 1) / B, B>>>();
    hist_kernel<<<(NNZE + B - 1) / B, B>>>(up_rows, pu_rows);
    scan1_kernel<<<NB_U, 1024>>>(pup_ptr, pup_off, NU);
    scan2_kernel<<<1, 256>>>(NB_U, pup_ptr + NU);
    scan3_kernel<<<NB_U, 1024>>>(pup_ptr, pup_off, NU);
    scan1_kernel<<<NB_P, 1024>>>(ppu_ptr, ppu_off, NP);
    scan2_kernel<<<1, 256>>>(NB_P, ppu_ptr + NP);
    scan3_kernel<<<NB_P, 1024>>>(ppu_ptr, ppu_off, NP);
    scatter_kernel<<<(NNZE + B - 1) / B, B>>>(up_rows, up_cols, up_vals,
                                              pu_rows, pu_cols, pu_vals);

    // bf16 mirror of layer-0 x (= pois)
    cvt_kernel<<<(NTOT / 4 + B - 1) / B, B>>>((const float4*)pois);

    // ---- 3 layers (lazy acc: out folded at last layer) ----
    // layer 0: x_in = pois -> x1 in g_xa
    spmm_up_kernel<<<(NU * 32) / B, B>>>();
    spmm_pu_fused_kernel<<<(NP * 32) / B, B>>>(pois, pxa, nullptr, nullptr,
                                               lk0[0], lk1[0], 0, out);
    // layer 1: x_in = x1 -> x2 in g_xb
    spmm_up_kernel<<<(NU * 32) / B, B>>>();
    spmm_pu_fused_kernel<<<(NP * 32) / B, B>>>(pxa, pxb, nullptr, nullptr,
                                               lk0[1], lk1[1], 0, out);
    // layer 2: x_in = x2; out = 0.25*(pois + x1 + x2 + x3)
    spmm_up_kernel<<<(NU * 32) / B, B>>>();
    spmm_pu_fused_kernel<<<(NP * 32) / B, B>>>(pxb, nullptr, pois, pxa,
                                               lk0[2], lk1[2], 1, out);
}

// round 11
// speedup vs baseline: 1.2199x; 1.0208x over previous
#include <cuda_runtime.h>
#include <cuda_bf16.h>
#include <cstdint>

#define NP   200000
#define NU   50000
#define NNZE 2000000
#define DIM  64
#define NTOT (NP*DIM)      /* 12,800,000 */
#define MSGN (NU*DIM)      /*  3,200,000 */

#define NB_U ((NU + 1023) / 1024)       /* 49  */
#define NB_P ((NP + 1023) / 1024)       /* 196 */
#define SC_BLOCKS ((NNZE + 255) / 256)  /* 7813 */
#define CVT_BLOCKS (NTOT / 4 / 256)     /* 12500 exact */
#define UP_BLOCKS (NU * 32 / 256)       /* 6250 exact */
#define PU_BLOCKS (NP * 32 / 256)       /* 25000 exact */

__device__ __align__(16) float g_xa[NTOT];                 // layer-1 x
__device__ __align__(16) float g_xb[NTOT];                 // layer-2 x
__device__ __align__(16) __nv_bfloat162 g_xh[NTOT / 2];    // bf16 mirror of current x
__device__ __align__(16) __nv_bfloat162 g_msgh[MSGN / 2];  // bf16 msg (gather operand)

// CSR scratch
__device__ int  g_up_ptr[NU + 1];
__device__ int  g_up_off[NU];
__device__ int2 g_up_cv[NNZE];     // packed (col, val-bits), row-grouped
__device__ int  g_pu_ptr[NP + 1];
__device__ int  g_pu_off[NP];
__device__ int2 g_pu_cv[NNZE];
__device__ int  g_bsum_u[64];
__device__ int  g_bsum_p[256];

// ---------------- threefry2x32 (exact JAX semantics) ----------------
__host__ __device__ __forceinline__ uint32_t rotl32(uint32_t x, int d) {
    return (x << d) | (x >> (32 - d));
}

__host__ __device__ __forceinline__ void tf2x32(uint32_t k0, uint32_t k1,
                                                uint32_t x0, uint32_t x1,
                                                uint32_t &o0, uint32_t &o1) {
    uint32_t ks2 = k0 ^ k1 ^ 0x1BD11BDAu;
    x0 += k0; x1 += k1;
#define TFR(r) { x0 += x1; x1 = rotl32(x1, (r)); x1 ^= x0; }
    TFR(13) TFR(15) TFR(26) TFR(6)
    x0 += k1;  x1 += ks2 + 1u;
    TFR(17) TFR(29) TFR(16) TFR(24)
    x0 += ks2; x1 += k0 + 2u;
    TFR(13) TFR(15) TFR(26) TFR(6)
    x0 += k0;  x1 += k1 + 3u;
    TFR(17) TFR(29) TFR(16) TFR(24)
    x0 += k1;  x1 += ks2 + 4u;
    TFR(13) TFR(15) TFR(26) TFR(6)
    x0 += ks2; x1 += k0 + 5u;
#undef TFR
    o0 = x0; o1 = x1;
}

// partitionable threefry draw for element e (counter (0, e)), 32-bit: out0 ^ out1
__device__ __forceinline__ uint32_t tf_bits(uint32_t k0, uint32_t k1, uint32_t e) {
    uint32_t o0, o1;
    tf2x32(k0, k1, 0u, e, o0, o1);
    return o0 ^ o1;
}

__device__ __forceinline__ float dropv(uint32_t bits, float s) {
    return (bits & 0x80000000u) ? 0.f : 2.f * s;   // keep iff MSB==0, scale 1/keep=2
}

// ---------------- CSR build ----------------
__global__ void zero_cnt_kernel() {
    int i = blockIdx.x * blockDim.x + threadIdx.x;
    if (i <= NU) g_up_ptr[i] = 0;
    if (i <= NP) g_pu_ptr[i] = 0;
}

__global__ void hist_kernel(const int* __restrict__ up_rows,
                            const int* __restrict__ pu_rows) {
    int e = blockIdx.x * blockDim.x + threadIdx.x;
    if (e >= NNZE) return;
    atomicAdd(&g_up_ptr[__ldg(up_rows + e)], 1);
    atomicAdd(&g_pu_ptr[__ldg(pu_rows + e)], 1);
}

// merged pass 1: blocks [0,NB_U) scan UP counts, [NB_U,NB_U+NB_P) scan PU counts
__global__ void scan1_kernel() {
    __shared__ int ws[32];
    int t = threadIdx.x;
    bool isU = blockIdx.x < NB_U;
    int lb = isU ? blockIdx.x : blockIdx.x - NB_U;
    int n  = isU ? NU : NP;
    const int* cnt = isU ? g_up_ptr : g_pu_ptr;
    int* excl      = isU ? g_up_off : g_pu_off;
    int* bsum      = isU ? g_bsum_u : g_bsum_p;

    int i = lb * 1024 + t;
    int v = (i < n) ? cnt[i] : 0;
    int x = v;
#pragma unroll
    for (int d = 1; d < 32; d <<= 1) {
        int u = __shfl_up_sync(~0u, x, d);
        if ((t & 31) >= d) x += u;
    }
    if ((t & 31) == 31) ws[t >> 5] = x;
    __syncthreads();
    if (t < 32) {
        int w = ws[t];
#pragma unroll
        for (int d = 1; d < 32; d <<= 1) {
            int u = __shfl_up_sync(~0u, w, d);
            if (t >= d) w += u;
        }
        ws[t] = w;
    }
    __syncthreads();
    int base = (t >= 32) ? ws[(t >> 5) - 1] : 0;
    int incl = x + base;
    if (i < n) excl[i] = incl - v;
    if (t == 1023) bsum[lb] = incl;
}

// merged pass 2: block 0 scans UP block sums, block 1 scans PU block sums
__global__ void scan2_kernel() {
    __shared__ int ws[8];
    bool isU = blockIdx.x == 0;
    int nb   = isU ? NB_U : NB_P;
    int* bsum  = isU ? g_bsum_u : g_bsum_p;
    int* ptr_n = isU ? &g_up_ptr[NU] : &g_pu_ptr[NP];

    int t = threadIdx.x;       // 256 threads
    int v = (t < nb) ? bsum[t] : 0;
    int x = v;
#pragma unroll
    for (int d = 1; d < 32; d <<= 1) {
        int u = __shfl_up_sync(~0u, x, d);
        if ((t & 31) >= d) x += u;
    }
    if ((t & 31) == 31) ws[t >> 5] = x;
    __syncthreads();
    if (t < 8) {
        int w = ws[t];
#pragma unroll
        for (int d = 1; d < 8; d <<= 1) {
            int u = __shfl_up_sync(0xffu, w, d);
            if (t >= d) w += u;
        }
        ws[t] = w;
    }
    __syncthreads();
    int base = (t >= 32) ? ws[(t >> 5) - 1] : 0;
    int incl = x + base;
    if (t < nb) bsum[t] = incl - v;
    if (t == nb - 1) *ptr_n = incl;
}

// merged pass 3: add block offset; write both ptr and off
__global__ void scan3_kernel() {
    bool isU = blockIdx.x < NB_U;
    int lb = isU ? blockIdx.x : blockIdx.x - NB_U;
    int n  = isU ? NU : NP;
    int* ptr = isU ? g_up_ptr : g_pu_ptr;
    int* off = isU ? g_up_off : g_pu_off;
    const int* bsum = isU ? g_bsum_u : g_bsum_p;

    int i = lb * 1024 + threadIdx.x;
    if (i < n) {
        int v = off[i] + bsum[lb];
        ptr[i] = v;
        off[i] = v;
    }
}

// ---------------- launch A: scatter UP entries || cvt pois -> bf16 ----------
__global__ void scatter_up_cvt_kernel(const int* __restrict__ up_rows,
                                      const int* __restrict__ up_cols,
                                      const float* __restrict__ up_vals,
                                      const float4* __restrict__ pois) {
    if (blockIdx.x < SC_BLOCKS) {
        int e = blockIdx.x * 256 + threadIdx.x;
        if (e >= NNZE) return;
        int r = __ldg(up_rows + e);
        int p = atomicAdd(&g_up_off[r], 1);
        g_up_cv[p] = make_int2(__ldg(up_cols + e), __float_as_int(__ldg(up_vals + e)));
    } else {
        int i = (blockIdx.x - SC_BLOCKS) * 256 + threadIdx.x;  // < NTOT/4 exact
        float4 v = pois[i];
        g_xh[2 * i]     = __floats2bfloat162_rn(v.x, v.y);
        g_xh[2 * i + 1] = __floats2bfloat162_rn(v.z, v.w);
    }
}

// ---------------- UP SpMM body (warp per U-row; bf16 gather, fp32 accum) ----
__device__ __forceinline__ void spmm_up_body(int w, int lane) {
    int s = __ldg(g_up_ptr + w), e = __ldg(g_up_ptr + w + 1);
    float accx = 0.f, accy = 0.f;
    for (int j = s; j < e; ++j) {
        int2 cv = __ldg(g_up_cv + j);                // same addr all lanes: broadcast
        float v = __int_as_float(cv.y);
        float2 xv = __bfloat1622float2(g_xh[(size_t)cv.x * (DIM / 2) + lane]);
        accx += v * xv.x;
        accy += v * xv.y;
    }
    g_msgh[(size_t)w * (DIM / 2) + lane] = __floats2bfloat162_rn(accx, accy);
}

// ---------------- launch B: UP SpMM layer 0 || scatter PU entries ----------
__global__ void up0_scatter_pu_kernel(const int* __restrict__ pu_rows,
                                      const int* __restrict__ pu_cols,
                                      const float* __restrict__ pu_vals) {
    if (blockIdx.x < UP_BLOCKS) {
        int w = (blockIdx.x * 256 + threadIdx.x) >> 5;   // < NU exact
        spmm_up_body(w, threadIdx.x & 31);
    } else {
        int e = (blockIdx.x - UP_BLOCKS) * 256 + threadIdx.x;
        if (e >= NNZE) return;
        int r = __ldg(pu_rows + e);
        int p = atomicAdd(&g_pu_off[r], 1);
        g_pu_cv[p] = make_int2(__ldg(pu_cols + e), __float_as_int(__ldg(pu_vals + e)));
    }
}

// plain UP SpMM for layers 1, 2
__global__ void spmm_up_kernel() {
    int w = (blockIdx.x * 256 + threadIdx.x) >> 5;       // < NU exact
    spmm_up_body(w, threadIdx.x & 31);
}

// ---------------- PU SpMM fused with residual + dropout (+ final mean) ------
// last==0: x_next = drop(prop + x_in); write x_next (fp32 -> x_out, bf16 -> g_xh)
// last==1: out = 0.25*(pois + x1 + x_in + drop(prop + x_in))
__global__ void spmm_pu_fused_kernel(const float* __restrict__ x_in,
                                     float* __restrict__ x_out,
                                     const float* __restrict__ pois_in,
                                     const float* __restrict__ x1_in,
                                     uint32_t k0, uint32_t k1, int last,
                                     float* __restrict__ out) {
    int w = (blockIdx.x * 256 + threadIdx.x) >> 5;       // < NP exact
    int lane = threadIdx.x & 31;
    int s = __ldg(g_pu_ptr + w), e = __ldg(g_pu_ptr + w + 1);
    float accx = 0.f, accy = 0.f;
    for (int j = s; j < e; ++j) {
        int2 cv = __ldg(g_pu_cv + j);                    // broadcast load
        float v = __int_as_float(cv.y);
        float2 xv = __bfloat1622float2(g_msgh[(size_t)cv.x * (DIM / 2) + lane]);
        accx += v * xv.x;
        accy += v * xv.y;
    }
    size_t idx = (size_t)w * DIM + lane * 2;
    uint32_t e0 = (uint32_t)idx;
    uint32_t b0 = tf_bits(k0, k1, e0);
    uint32_t b1 = tf_bits(k0, k1, e0 + 1u);

    float2 xv = *reinterpret_cast<const float2*>(x_in + idx);
    float n0 = dropv(b0, accx + xv.x);
    float n1 = dropv(b1, accy + xv.y);

    if (last) {
        float2 pv = *reinterpret_cast<const float2*>(pois_in + idx);
        float2 x1 = *reinterpret_cast<const float2*>(x1_in + idx);
        *reinterpret_cast<float2*>(out + idx) =
            make_float2((pv.x + x1.x + xv.x + n0) * 0.25f,
                        (pv.y + x1.y + xv.y + n1) * 0.25f);
    } else {
        *reinterpret_cast<float2*>(x_out + idx) = make_float2(n0, n1);
        g_xh[idx / 2] = __floats2bfloat162_rn(n0, n1);
    }
}

// ---------------- launch ----------------
// Inputs in dict/insertion order:
//   d_in[0]=pois_embs, d_in[1]=up_rows, d_in[2]=up_cols, d_in[3]=up_vals,
//   d_in[4]=pu_rows,   d_in[5]=pu_cols, d_in[6]=pu_vals
extern "C" void kernel_launch(void* const* d_in, const int* in_sizes, int n_in,
                              void* d_out, int out_size) {
    const float* pois    = (const float*)d_in[0];
    const int*   up_rows = (const int*)  d_in[1];
    const int*   up_cols = (const int*)  d_in[2];
    const float* up_vals = (const float*)d_in[3];
    const int*   pu_rows = (const int*)  d_in[4];
    const int*   pu_cols = (const int*)  d_in[5];
    const float* pu_vals = (const float*)d_in[6];
    float* out = (float*)d_out;

    float *pxa, *pxb;
    cudaGetSymbolAddress((void**)&pxa, g_xa);
    cudaGetSymbolAddress((void**)&pxb, g_xb);

    // per-layer dropout keys: fold_in(key(42), l) = threefry((0,42),(0,l))
    uint32_t lk0[3], lk1[3];
    for (int l = 0; l < 3; ++l)
        tf2x32(0u, 42u, 0u, (uint32_t)l, lk0[l], lk1[l]);

    const int B = 256;

    // ---- CSR build (once per call, reused by all 3 layers) ----
    zero_cnt_kernel<<<(NP + 1 + B - 1) / B, B>>>();
    hist_kernel<<<SC_BLOCKS, B>>>(up_rows, pu_rows);
    scan1_kernel<<<NB_U + NB_P, 1024>>>();
    scan2_kernel<<<2, 256>>>();
    scan3_kernel<<<NB_U + NB_P, 1024>>>();

    // launch A: scatter UP || cvt pois->bf16
    scatter_up_cvt_kernel<<<SC_BLOCKS + CVT_BLOCKS, B>>>(up_rows, up_cols, up_vals,
                                                         (const float4*)pois);
    // launch B: UP SpMM layer 0 || scatter PU
    up0_scatter_pu_kernel<<<UP_BLOCKS + SC_BLOCKS, B>>>(pu_rows, pu_cols, pu_vals);

    // ---- layers (lazy acc: mean folded at last layer) ----
    // layer 0 PU: x_in = pois -> x1 in g_xa
    spmm_pu_fused_kernel<<<PU_BLOCKS, B>>>(pois, pxa, nullptr, nullptr,
                                           lk0[0], lk1[0], 0, out);
    // layer 1
    spmm_up_kernel<<<UP_BLOCKS, B>>>();
    spmm_pu_fused_kernel<<<PU_BLOCKS, B>>>(pxa, pxb, nullptr, nullptr,
                                           lk0[1], lk1[1], 0, out);
    // layer 2: out = 0.25*(pois + x1 + x2 + x3)
    spmm_up_kernel<<<UP_BLOCKS, B>>>();
    spmm_pu_fused_kernel<<<PU_BLOCKS, B>>>(pxb, nullptr, pois, pxa,
                                           lk0[2], lk1[2], 1, out);
}